// round 13
// baseline (speedup 1.0000x reference)
#include <cuda_runtime.h>
#include <math.h>

typedef unsigned long long u64;

// ---------------- device scratch (no allocations allowed) ----------------
__device__ float g_agg[25000 * 128]; // segment-sum of edge_feat
__device__ float g_P1 [25000 * 128]; // h @ e_W1[0:128] + e_b1
__device__ float g_P2 [25000 * 128]; // h @ e_W1[128:256]
__device__ int   g_idx64;            // 1 if edge_index is int64

// ---------------- packed f32x2 helpers ----------------
__device__ __forceinline__ u64 pk2(float lo, float hi) {
    u64 r; asm("mov.b64 %0,{%1,%2};" : "=l"(r) : "f"(lo), "f"(hi)); return r;
}
__device__ __forceinline__ void upk2(u64 v, float& lo, float& hi) {
    asm("mov.b64 {%0,%1},%2;" : "=f"(lo), "=f"(hi) : "l"(v));
}
__device__ __forceinline__ u64 fma2(u64 a, u64 b, u64 c) {
    u64 d; asm("fma.rn.f32x2 %0,%1,%2,%3;" : "=l"(d) : "l"(a), "l"(b), "l"(c)); return d;
}
__device__ __forceinline__ u64 add2(u64 a, u64 b) {
    u64 d; asm("add.rn.f32x2 %0,%1,%2;" : "=l"(d) : "l"(a), "l"(b)); return d;
}
__device__ __forceinline__ u64 mul2(u64 a, u64 b) {
    u64 d; asm("mul.rn.f32x2 %0,%1,%2;" : "=l"(d) : "l"(a), "l"(b)); return d;
}
__device__ __forceinline__ void barp(int id) {
    asm volatile("bar.sync %0, 64;" :: "r"(id) : "memory");
}

// ---------------- init: idx detect, zero agg, seed coord_out ----------------
__global__ void init_kernel(const float* __restrict__ coord, float* __restrict__ coord_out,
                            const unsigned* __restrict__ ei, int N) {
    int i = blockIdx.x * blockDim.x + threadIdx.x;
    if (i == 0) {
        int f = 1;
        for (int t = 0; t < 64; t++) if (ei[2 * t + 1] != 0u) { f = 0; break; }
        g_idx64 = f;
    }
    if (i < N * 128) g_agg[i] = 0.0f;
    if (i < N * 3)   coord_out[i] = coord[i];
}

// ======================= full-width warp GEMM (pre/node kernels) =======================
template <int K>
__device__ __forceinline__ void gemm_k(const float* __restrict__ sw,
                                       const float* __restrict__ W,
                                       int l, u64 acc[8][4]) {
    const float* wb = W + l;
#pragma unroll 4
    for (int k = 0; k < K; k++) {
        const float* wr = wb + k * 128;
        float f0 = __ldg(wr);
        float f1 = __ldg(wr + 32);
        float f2 = __ldg(wr + 64);
        float f3 = __ldg(wr + 96);
        const float4* a = (const float4*)(sw + k * 20);
        float4 A0 = a[0], A1 = a[1], A2 = a[2], A3 = a[3];
        u64 x[8];
        x[0] = ((const u64*)&A0)[0]; x[1] = ((const u64*)&A0)[1];
        x[2] = ((const u64*)&A1)[0]; x[3] = ((const u64*)&A1)[1];
        x[4] = ((const u64*)&A2)[0]; x[5] = ((const u64*)&A2)[1];
        x[6] = ((const u64*)&A3)[0]; x[7] = ((const u64*)&A3)[1];
        u64 w0 = pk2(f0, f0), w1 = pk2(f1, f1), w2 = pk2(f2, f2), w3 = pk2(f3, f3);
#pragma unroll
        for (int p = 0; p < 8; p++) {
            acc[p][0] = fma2(x[p], w0, acc[p][0]);
            acc[p][1] = fma2(x[p], w1, acc[p][1]);
            acc[p][2] = fma2(x[p], w2, acc[p][2]);
            acc[p][3] = fma2(x[p], w3, acc[p][3]);
        }
    }
}

__device__ __forceinline__ void init_bias(u64 acc[8][4], const float* __restrict__ b, int l) {
#pragma unroll
    for (int j = 0; j < 4; j++) {
        float bb = __ldg(b + l + 32 * j);
        u64 v = pk2(bb, bb);
#pragma unroll
        for (int p = 0; p < 8; p++) acc[p][j] = v;
    }
}

__device__ __forceinline__ void init_zero(u64 acc[8][4]) {
#pragma unroll
    for (int j = 0; j < 4; j++)
#pragma unroll
        for (int p = 0; p < 8; p++) acc[p][j] = 0ull;
}

__device__ __forceinline__ void ln_silu(u64 acc[8][4],
                                        const float* __restrict__ g,
                                        const float* __restrict__ be, int l) {
    float gv[4], bv[4];
#pragma unroll
    for (int j = 0; j < 4; j++) { gv[j] = __ldg(g + l + 32 * j); bv[j] = __ldg(be + l + 32 * j); }
#pragma unroll
    for (int p = 0; p < 8; p++) {
        u64 s1 = add2(add2(acc[p][0], acc[p][1]), add2(acc[p][2], acc[p][3]));
        u64 s2 = mul2(acc[p][0], acc[p][0]);
        s2 = fma2(acc[p][1], acc[p][1], s2);
        s2 = fma2(acc[p][2], acc[p][2], s2);
        s2 = fma2(acc[p][3], acc[p][3], s2);
#pragma unroll
        for (int o = 16; o > 0; o >>= 1) {
            s1 = add2(s1, __shfl_xor_sync(0xffffffffu, s1, o));
            s2 = add2(s2, __shfl_xor_sync(0xffffffffu, s2, o));
        }
        float m0, m1, q0, q1;
        upk2(s1, m0, m1); upk2(s2, q0, q1);
        const float inv = 1.0f / 128.0f;
        m0 *= inv; m1 *= inv;
        float v0 = q0 * inv - m0 * m0, v1 = q1 * inv - m1 * m1;
        float r0 = rsqrtf(v0 + 1e-5f), r1 = rsqrtf(v1 + 1e-5f);
#pragma unroll
        for (int j = 0; j < 4; j++) {
            float x0, x1; upk2(acc[p][j], x0, x1);
            x0 = (x0 - m0) * r0 * gv[j] + bv[j];
            x1 = (x1 - m1) * r1 * gv[j] + bv[j];
            x0 = x0 * __fdividef(1.0f, 1.0f + __expf(-x0));
            x1 = x1 * __fdividef(1.0f, 1.0f + __expf(-x1));
            acc[p][j] = pk2(x0, x1);
        }
    }
}

__device__ __forceinline__ void store_tile(float* __restrict__ sw, u64 acc[8][4], int l) {
#pragma unroll
    for (int j = 0; j < 4; j++) {
        int c = l + 32 * j;
        u64* d = (u64*)(sw + c * 20);
#pragma unroll
        for (int p = 0; p < 8; p++) d[p] = acc[p][j];
    }
}

static const int TILE_F  = 2640;
static const int SMEM_B  = (4 * TILE_F + 4 * 128) * 4;  // pre/node kernels

// ======================= split-channel warp-pair machinery (edge kernel) =======================
// Warp pair q = {half 0, half 1}; warp owns channels cb+32j+l, cb = half*64, j in {0,1}.
template <int K>
__device__ __forceinline__ void gemm_k2(const float* __restrict__ sw,
                                        const float* __restrict__ W,  // already + cb
                                        int l, u64 acc[8][2]) {
    const float* wb = W + l;
#pragma unroll 4
    for (int k = 0; k < K; k++) {
        const float* wr = wb + k * 128;
        float f0 = __ldg(wr);
        float f1 = __ldg(wr + 32);
        const float4* a = (const float4*)(sw + k * 20);
        float4 A0 = a[0], A1 = a[1], A2 = a[2], A3 = a[3];
        u64 x[8];
        x[0] = ((const u64*)&A0)[0]; x[1] = ((const u64*)&A0)[1];
        x[2] = ((const u64*)&A1)[0]; x[3] = ((const u64*)&A1)[1];
        x[4] = ((const u64*)&A2)[0]; x[5] = ((const u64*)&A2)[1];
        x[6] = ((const u64*)&A3)[0]; x[7] = ((const u64*)&A3)[1];
        u64 w0 = pk2(f0, f0), w1 = pk2(f1, f1);
#pragma unroll
        for (int p = 0; p < 8; p++) {
            acc[p][0] = fma2(x[p], w0, acc[p][0]);
            acc[p][1] = fma2(x[p], w1, acc[p][1]);
        }
    }
}

__device__ __forceinline__ void init_bias2(u64 acc[8][2], const float* __restrict__ b, int cl) {
#pragma unroll
    for (int j = 0; j < 2; j++) {
        float bb = __ldg(b + cl + 32 * j);
        u64 v = pk2(bb, bb);
#pragma unroll
        for (int p = 0; p < 8; p++) acc[p][j] = v;
    }
}

// cross-warp LN+silu: exch = 32-u64 buffer per pair ([half*16 + 2p], [.. +1])
__device__ __forceinline__ void ln_silu2(u64 acc[8][2],
                                         const float* __restrict__ g,
                                         const float* __restrict__ be,
                                         int l, int cl, u64* exch, int half, int barid) {
    float gv[2], bv[2];
#pragma unroll
    for (int j = 0; j < 2; j++) { gv[j] = __ldg(g + cl + 32 * j); bv[j] = __ldg(be + cl + 32 * j); }
    // phase 1: per-pair partial sums over this warp's 64 channels
#pragma unroll
    for (int p = 0; p < 8; p++) {
        u64 s1 = add2(acc[p][0], acc[p][1]);
        u64 s2 = fma2(acc[p][1], acc[p][1], mul2(acc[p][0], acc[p][0]));
#pragma unroll
        for (int o = 16; o > 0; o >>= 1) {
            s1 = add2(s1, __shfl_xor_sync(0xffffffffu, s1, o));
            s2 = add2(s2, __shfl_xor_sync(0xffffffffu, s2, o));
        }
        if (l == 0) { exch[half * 16 + 2 * p] = s1; exch[half * 16 + 2 * p + 1] = s2; }
    }
    barp(barid);
    // phase 2: combine halves, normalize
#pragma unroll
    for (int p = 0; p < 8; p++) {
        u64 S1 = add2(exch[2 * p],     exch[16 + 2 * p]);
        u64 S2 = add2(exch[2 * p + 1], exch[16 + 2 * p + 1]);
        float m0, m1, q0, q1;
        upk2(S1, m0, m1); upk2(S2, q0, q1);
        const float inv = 1.0f / 128.0f;
        m0 *= inv; m1 *= inv;
        float v0 = q0 * inv - m0 * m0, v1 = q1 * inv - m1 * m1;
        float r0 = rsqrtf(v0 + 1e-5f), r1 = rsqrtf(v1 + 1e-5f);
#pragma unroll
        for (int j = 0; j < 2; j++) {
            float x0, x1; upk2(acc[p][j], x0, x1);
            x0 = (x0 - m0) * r0 * gv[j] + bv[j];
            x1 = (x1 - m1) * r1 * gv[j] + bv[j];
            x0 = x0 * __fdividef(1.0f, 1.0f + __expf(-x0));
            x1 = x1 * __fdividef(1.0f, 1.0f + __expf(-x1));
            acc[p][j] = pk2(x0, x1);
        }
    }
}

__device__ __forceinline__ void store_tile2(float* __restrict__ sw, u64 acc[8][2], int cl) {
#pragma unroll
    for (int j = 0; j < 2; j++) {
        int c = cl + 32 * j;
        u64* d = (u64*)(sw + c * 20);
#pragma unroll
        for (int p = 0; p < 8; p++) d[p] = acc[p][j];
    }
}

// edge kernel smem: 2 pairs x (tile 2560 + meta 128 + exch 64 + exch2 32 floats)
static const int PTILE_F   = 2560;
static const int PMETA_F   = 224;
static const int SMEM_EB   = (2 * PTILE_F + 2 * PMETA_F) * 4;  // 22272 bytes

// ---------------- pre kernel: P1 = h@W1a + b1, P2 = h@W1b ----------------
__global__ __launch_bounds__(128, 3)
void pre_kernel(const float* __restrict__ h, const float* __restrict__ eW1,
                const float* __restrict__ e_b1, int N) {
    extern __shared__ float smem[];
    int w = threadIdx.x >> 5, l = threadIdx.x & 31;
    float* sw = smem + w * TILE_F;
    int base = blockIdx.x * 64 + w * 16;

#pragma unroll 1
    for (int e = 0; e < 16; e++) {
        int n = base + e; int nc = (n < N) ? n : 0;
#pragma unroll
        for (int m = 0; m < 4; m++) {
            int k = l + 32 * m;
            sw[k * 20 + e] = __ldg(h + (size_t)nc * 128 + k);
        }
    }
    __syncwarp();

    u64 acc[8][4];
    init_bias(acc, e_b1, l);
    gemm_k<128>(sw, eW1, l, acc);
#pragma unroll
    for (int p = 0; p < 8; p++) {
        int n0 = base + 2 * p, n1 = n0 + 1;
#pragma unroll
        for (int j = 0; j < 4; j++) {
            float x0, x1; upk2(acc[p][j], x0, x1);
            int c = l + 32 * j;
            if (n0 < N) g_P1[(size_t)n0 * 128 + c] = x0;
            if (n1 < N) g_P1[(size_t)n1 * 128 + c] = x1;
        }
    }

    init_zero(acc);
    gemm_k<128>(sw, eW1 + 128 * 128, l, acc);
#pragma unroll
    for (int p = 0; p < 8; p++) {
        int n0 = base + 2 * p, n1 = n0 + 1;
#pragma unroll
        for (int j = 0; j < 4; j++) {
            float x0, x1; upk2(acc[p][j], x0, x1);
            int c = l + 32 * j;
            if (n0 < N) g_P2[(size_t)n0 * 128 + c] = x0;
            if (n1 < N) g_P2[(size_t)n1 * 128 + c] = x1;
        }
    }
}

// ---------------- edge kernel: 32 edges / block, 2 warp-pairs ----------------
__global__ __launch_bounds__(128, 4)
void edge_kernel(const void* __restrict__ ei,
                 const float* __restrict__ coord, const float* __restrict__ eattr,
                 const float* __restrict__ eW1,
                 const float* __restrict__ e_g1, const float* __restrict__ e_be1,
                 const float* __restrict__ eW2,
                 const float* __restrict__ e_b2, const float* __restrict__ e_g2, const float* __restrict__ e_be2,
                 const float* __restrict__ cW1,
                 const float* __restrict__ c_b1, const float* __restrict__ c_g1, const float* __restrict__ c_be1,
                 const float* __restrict__ cW2,
                 float* __restrict__ coord_out, int E) {
    extern __shared__ float smem[];
    int tid = threadIdx.x, w = tid >> 5, l = tid & 31;
    int q = w >> 1, half = w & 1;
    int barid = q + 1;
    int cb = half * 64;        // channel base for this warp
    int cl = cb + l;           // lane channel (j adds 32)

    float* sw    = smem + q * PTILE_F;
    float* meta  = smem + 2 * PTILE_F + q * PMETA_F;
    int*   srow  = (int*)meta;          // gather-safe row
    int*   svrow = (int*)meta + 16;     // -1 if invalid edge
    int*   scol  = (int*)meta + 32;
    float* scd   = meta + 48;           // 48 floats
    float* srad  = meta + 96;           // 16, 8B aligned
    float* sea   = meta + 112;          // 16
    u64*   exch  = (u64*)(meta + 128);  // 32 u64 (LN sums)
    u64*   exch2 = exch + 32;           // 16 u64 (coord dot)

    int base = blockIdx.x * 32 + q * 16;

    if (half == 0 && l < 16) {
        int e = base + l;
        bool v = e < E;
        int ec = v ? e : 0;
        int r, c;
        if (g_idx64) {
            const long long* qq = (const long long*)ei;
            r = (int)qq[ec]; c = (int)qq[(size_t)E + ec];
        } else {
            const int* qq = (const int*)ei;
            r = qq[ec]; c = qq[E + ec];
        }
        float dx = coord[r * 3 + 0] - coord[c * 3 + 0];
        float dy = coord[r * 3 + 1] - coord[c * 3 + 1];
        float dz = coord[r * 3 + 2] - coord[c * 3 + 2];
        float radial = dx * dx + dy * dy + dz * dz;
        float invn = 1.0f / (sqrtf(radial + 1e-8f) + 1.0f);
        srow[l]  = r;
        svrow[l] = v ? r : -1;
        scol[l]  = c;
        scd[l * 3 + 0] = dx * invn;
        scd[l * 3 + 1] = dy * invn;
        scd[l * 3 + 2] = dz * invn;
        srad[l] = radial;
        sea[l]  = eattr[ec];
    }
    barp(barid);

    u64 acc[8][2];

    // ---- layer 1 DIRECT: P1[row] + P2[col] + radial*W[256] + ea*W[257] (this channel half) ----
    {
        float w6[2], w7[2];
#pragma unroll
        for (int j = 0; j < 2; j++) {
            w6[j] = __ldg(eW1 + 256 * 128 + cl + 32 * j);
            w7[j] = __ldg(eW1 + 257 * 128 + cl + 32 * j);
        }
#pragma unroll
        for (int p = 0; p < 8; p++) {
            int r0 = srow[2 * p], r1 = srow[2 * p + 1];
            int c0 = scol[2 * p], c1 = scol[2 * p + 1];
            const float* p1a = g_P1 + (size_t)r0 * 128 + cl;
            const float* p1b = g_P1 + (size_t)r1 * 128 + cl;
            const float* p2a = g_P2 + (size_t)c0 * 128 + cl;
            const float* p2b = g_P2 + (size_t)c1 * 128 + cl;
            u64 rad2 = *(const u64*)(srad + 2 * p);
            u64 ea2  = *(const u64*)(sea  + 2 * p);
#pragma unroll
            for (int j = 0; j < 2; j++) {
                float a0 = __ldg(p1a + 32 * j) + __ldg(p2a + 32 * j);
                float a1 = __ldg(p1b + 32 * j) + __ldg(p2b + 32 * j);
                u64 v = pk2(a0, a1);
                v = fma2(rad2, pk2(w6[j], w6[j]), v);
                v = fma2(ea2,  pk2(w7[j], w7[j]), v);
                acc[p][j] = v;
            }
        }
    }
    ln_silu2(acc, e_g1, e_be1, l, cl, exch, half, barid);
    store_tile2(sw, acc, cl);
    barp(barid);

    // ---- layer 2 -> edge_feat ----
    init_bias2(acc, e_b2, cl);
    gemm_k2<128>(sw, eW2 + cb, l, acc);
    ln_silu2(acc, e_g2, e_be2, l, cl, exch, half, barid);  // internal bar also fences tile reads

    // scatter edge_feat into agg (coalesced channels per j)
#pragma unroll
    for (int p = 0; p < 8; p++) {
        int r0 = svrow[2 * p], r1 = svrow[2 * p + 1];
#pragma unroll
        for (int j = 0; j < 2; j++) {
            float x0, x1; upk2(acc[p][j], x0, x1);
            int c = cl + 32 * j;
            if (r0 >= 0) atomicAdd(&g_agg[(size_t)r0 * 128 + c], x0);
            if (r1 >= 0) atomicAdd(&g_agg[(size_t)r1 * 128 + c], x1);
        }
    }
    store_tile2(sw, acc, cl);
    barp(barid);

    // ---- coord MLP ----
    init_bias2(acc, c_b1, cl);
    gemm_k2<128>(sw, cW1 + cb, l, acc);
    ln_silu2(acc, c_g1, c_be1, l, cl, exch, half, barid);

    // dot with cW2 (half-dots exchanged through exch2)
    {
        float wv[2];
#pragma unroll
        for (int j = 0; j < 2; j++) wv[j] = __ldg(cW2 + cl + 32 * j);
#pragma unroll
        for (int p = 0; p < 8; p++) {
            u64 s = fma2(acc[p][1], pk2(wv[1], wv[1]), mul2(acc[p][0], pk2(wv[0], wv[0])));
#pragma unroll
            for (int o = 16; o > 0; o >>= 1)
                s = add2(s, __shfl_xor_sync(0xffffffffu, s, o));
            if (l == 0) exch2[half * 8 + p] = s;
        }
        barp(barid);
        if (half == 0 && l < 16) {
            u64 S = add2(exch2[l >> 1], exch2[8 + (l >> 1)]);
            float c0, c1; upk2(S, c0, c1);
            float cmv = (l & 1) ? c1 : c0;
            int r = svrow[l];
            if (r >= 0) {
                atomicAdd(&coord_out[(size_t)r * 3 + 0], scd[l * 3 + 0] * cmv);
                atomicAdd(&coord_out[(size_t)r * 3 + 1], scd[l * 3 + 1] * cmv);
                atomicAdd(&coord_out[(size_t)r * 3 + 2], scd[l * 3 + 2] * cmv);
            }
        }
    }
}

// ---------------- node kernel: 64 nodes / block (unchanged) ----------------
__global__ __launch_bounds__(128, 3)
void node_kernel(const float* __restrict__ h,
                 const float* __restrict__ nW1,
                 const float* __restrict__ n_b1, const float* __restrict__ n_g1,
                 const float* __restrict__ n_be1,
                 const float* __restrict__ nW2, const float* __restrict__ n_b2,
                 float* __restrict__ out, int N) {
    extern __shared__ float smem[];
    int w = threadIdx.x >> 5, l = threadIdx.x & 31;
    float* sw = smem + w * TILE_F;
    int base = blockIdx.x * 64 + w * 16;

    u64 acc[8][4];
    init_bias(acc, n_b1, l);

#pragma unroll 1
    for (int e = 0; e < 16; e++) {
        int n = base + e; int nc = (n < N) ? n : 0;
#pragma unroll
        for (int m = 0; m < 4; m++) {
            int k = l + 32 * m;
            sw[k * 20 + e] = __ldg(h + (size_t)nc * 128 + k);
        }
    }
    __syncwarp();
    gemm_k<128>(sw, nW1, l, acc);
    __syncwarp();

#pragma unroll 1
    for (int e = 0; e < 16; e++) {
        int n = base + e; int nc = (n < N) ? n : 0;
#pragma unroll
        for (int m = 0; m < 4; m++) {
            int k = l + 32 * m;
            sw[k * 20 + e] = g_agg[(size_t)nc * 128 + k];
        }
    }
    __syncwarp();
    gemm_k<128>(sw, nW1 + 128 * 128, l, acc);
    ln_silu(acc, n_g1, n_be1, l);
    __syncwarp();
    store_tile(sw, acc, l);
    __syncwarp();

    init_bias(acc, n_b2, l);
    gemm_k<128>(sw, nW2, l, acc);

#pragma unroll
    for (int p = 0; p < 8; p++) {
        int n0 = base + 2 * p, n1 = n0 + 1;
#pragma unroll
        for (int j = 0; j < 4; j++) {
            float x0, x1; upk2(acc[p][j], x0, x1);
            int c = l + 32 * j;
            if (n0 < N) out[(size_t)n0 * 128 + c] = x0 + __ldg(h + (size_t)n0 * 128 + c);
            if (n1 < N) out[(size_t)n1 * 128 + c] = x1 + __ldg(h + (size_t)n1 * 128 + c);
        }
    }
}

// ---------------- launch ----------------
extern "C" void kernel_launch(void* const* d_in, const int* in_sizes, int n_in,
                              void* d_out, int out_size) {
    const float* h     = (const float*)d_in[0];
    const void*  ei    = d_in[1];
    const float* coord = (const float*)d_in[2];
    const float* eattr = (const float*)d_in[3];
    const float* eW1  = (const float*)d_in[4];
    const float* eb1  = (const float*)d_in[5];
    const float* eg1  = (const float*)d_in[6];
    const float* ebe1 = (const float*)d_in[7];
    const float* eW2  = (const float*)d_in[8];
    const float* eb2  = (const float*)d_in[9];
    const float* eg2  = (const float*)d_in[10];
    const float* ebe2 = (const float*)d_in[11];
    const float* nW1  = (const float*)d_in[12];
    const float* nb1  = (const float*)d_in[13];
    const float* ng1  = (const float*)d_in[14];
    const float* nbe1 = (const float*)d_in[15];
    const float* nW2  = (const float*)d_in[16];
    const float* nb2  = (const float*)d_in[17];
    const float* cW1  = (const float*)d_in[18];
    const float* cb1  = (const float*)d_in[19];
    const float* cg1  = (const float*)d_in[20];
    const float* cbe1 = (const float*)d_in[21];
    const float* cW2  = (const float*)d_in[22];

    int N = in_sizes[0] / 128;
    int E = in_sizes[1] / 2;

    float* out       = (float*)d_out;
    float* coord_out = out + (size_t)N * 128;

    cudaFuncSetAttribute(pre_kernel,  cudaFuncAttributeMaxDynamicSharedMemorySize, SMEM_B);
    cudaFuncSetAttribute(edge_kernel, cudaFuncAttributeMaxDynamicSharedMemorySize, SMEM_EB);
    cudaFuncSetAttribute(node_kernel, cudaFuncAttributeMaxDynamicSharedMemorySize, SMEM_B);

    init_kernel<<<(N * 128 + 255) / 256, 256>>>(coord, coord_out, (const unsigned*)ei, N);
    pre_kernel<<<(N + 63) / 64, 128, SMEM_B>>>(h, eW1, eb1, N);
    edge_kernel<<<(E + 31) / 32, 128, SMEM_EB>>>(ei, coord, eattr,
                                                 eW1, eg1, ebe1,
                                                 eW2, eb2, eg2, ebe2,
                                                 cW1, cb1, cg1, cbe1, cW2,
                                                 coord_out, E);
    node_kernel<<<(N + 63) / 64, 128, SMEM_B>>>(h, nW1, nb1, ng1, nbe1, nW2, nb2, out, N);
}

// round 14
// speedup vs baseline: 1.6950x; 1.6950x over previous
#include <cuda_runtime.h>
#include <math.h>

typedef unsigned long long u64;

// ---------------- device scratch (no allocations allowed) ----------------
__device__ float g_agg[25000 * 128]; // segment-sum of edge_feat
__device__ float g_P1 [25000 * 128]; // h @ e_W1[0:128] + e_b1
__device__ float g_P2 [25000 * 128]; // h @ e_W1[128:256]
__device__ u64   g_Wd [131072];      // duplicated-packed weights (1 MB)
__device__ int   g_idx64;            // 1 if edge_index is int64

// region offsets inside g_Wd (u64 units)
#define WD_EW1  0        // eW1 rows 0..255   (256*128)
#define WD_EW2  32768    // eW2               (128*128)
#define WD_CW1  49152    // cW1               (128*128)
#define WD_NW1  65536    // nW1 rows 0..255   (256*128)
#define WD_NW2  98304    // nW2               (128*128)

// ---------------- packed f32x2 helpers ----------------
__device__ __forceinline__ u64 pk2(float lo, float hi) {
    u64 r; asm("mov.b64 %0,{%1,%2};" : "=l"(r) : "f"(lo), "f"(hi)); return r;
}
__device__ __forceinline__ void upk2(u64 v, float& lo, float& hi) {
    asm("mov.b64 {%0,%1},%2;" : "=f"(lo), "=f"(hi) : "l"(v));
}
__device__ __forceinline__ u64 fma2(u64 a, u64 b, u64 c) {
    u64 d; asm("fma.rn.f32x2 %0,%1,%2,%3;" : "=l"(d) : "l"(a), "l"(b), "l"(c)); return d;
}
__device__ __forceinline__ u64 add2(u64 a, u64 b) {
    u64 d; asm("add.rn.f32x2 %0,%1,%2;" : "=l"(d) : "l"(a), "l"(b)); return d;
}
__device__ __forceinline__ u64 mul2(u64 a, u64 b) {
    u64 d; asm("mul.rn.f32x2 %0,%1,%2;" : "=l"(d) : "l"(a), "l"(b)); return d;
}

// ---------------- init: idx detect, zero agg, seed coord_out ----------------
__global__ void init_kernel(const float* __restrict__ coord, float* __restrict__ coord_out,
                            const unsigned* __restrict__ ei, int N) {
    int i = blockIdx.x * blockDim.x + threadIdx.x;
    if (i == 0) {
        int f = 1;
        for (int t = 0; t < 64; t++) if (ei[2 * t + 1] != 0u) { f = 0; break; }
        g_idx64 = f;
    }
    if (i < N * 128) g_agg[i] = 0.0f;
    if (i < N * 3)   coord_out[i] = coord[i];
}

// ---------------- prep: duplicate-pack all GEMM weights ----------------
__global__ void prep_kernel(const float* __restrict__ eW1, const float* __restrict__ eW2,
                            const float* __restrict__ cW1, const float* __restrict__ nW1,
                            const float* __restrict__ nW2) {
    int t = blockIdx.x * blockDim.x + threadIdx.x;
    if (t >= 131072) return;
    float v;
    if      (t < WD_EW2) v = eW1[t];
    else if (t < WD_CW1) v = eW2[t - WD_EW2];
    else if (t < WD_NW1) v = cW1[t - WD_CW1];
    else if (t < WD_NW2) v = nW1[t - WD_NW1];
    else                 v = nW2[t - WD_NW2];
    g_Wd[t] = pk2(v, v);
}

// ============ core warp-level GEMM: 16 rows (8 f32x2 pairs) x 128 ch ============
// sw tile: row k (stride 20 floats), cols 0..15 = rows (pairs adjacent).
// Wd: duplicated-packed weights [K][128] u64; lane l owns channels l,l+32,l+64,l+96.
template <int K>
__device__ __forceinline__ void gemm_k(const float* __restrict__ sw,
                                       const u64* __restrict__ Wd,
                                       int l, u64 acc[8][4]) {
    const u64* wb = Wd + l;
#pragma unroll 4
    for (int k = 0; k < K; k++) {
        const u64* wr = wb + k * 128;
        u64 w0 = __ldg(wr);
        u64 w1 = __ldg(wr + 32);
        u64 w2 = __ldg(wr + 64);
        u64 w3 = __ldg(wr + 96);
        const float4* a = (const float4*)(sw + k * 20);
        float4 A0 = a[0], A1 = a[1], A2 = a[2], A3 = a[3];
        u64 x[8];
        x[0] = ((const u64*)&A0)[0]; x[1] = ((const u64*)&A0)[1];
        x[2] = ((const u64*)&A1)[0]; x[3] = ((const u64*)&A1)[1];
        x[4] = ((const u64*)&A2)[0]; x[5] = ((const u64*)&A2)[1];
        x[6] = ((const u64*)&A3)[0]; x[7] = ((const u64*)&A3)[1];
#pragma unroll
        for (int p = 0; p < 8; p++) {
            acc[p][0] = fma2(x[p], w0, acc[p][0]);
            acc[p][1] = fma2(x[p], w1, acc[p][1]);
            acc[p][2] = fma2(x[p], w2, acc[p][2]);
            acc[p][3] = fma2(x[p], w3, acc[p][3]);
        }
    }
}

__device__ __forceinline__ void init_bias(u64 acc[8][4], const float* __restrict__ b, int l) {
#pragma unroll
    for (int j = 0; j < 4; j++) {
        float bb = __ldg(b + l + 32 * j);
        u64 v = pk2(bb, bb);
#pragma unroll
        for (int p = 0; p < 8; p++) acc[p][j] = v;
    }
}

__device__ __forceinline__ void init_zero(u64 acc[8][4]) {
#pragma unroll
    for (int j = 0; j < 4; j++)
#pragma unroll
        for (int p = 0; p < 8; p++) acc[p][j] = 0ull;
}

__device__ __forceinline__ void ln_silu(u64 acc[8][4],
                                        const float* __restrict__ g,
                                        const float* __restrict__ be, int l) {
    float gv[4], bv[4];
#pragma unroll
    for (int j = 0; j < 4; j++) { gv[j] = __ldg(g + l + 32 * j); bv[j] = __ldg(be + l + 32 * j); }
#pragma unroll
    for (int p = 0; p < 8; p++) {
        u64 s1 = add2(add2(acc[p][0], acc[p][1]), add2(acc[p][2], acc[p][3]));
        u64 s2 = mul2(acc[p][0], acc[p][0]);
        s2 = fma2(acc[p][1], acc[p][1], s2);
        s2 = fma2(acc[p][2], acc[p][2], s2);
        s2 = fma2(acc[p][3], acc[p][3], s2);
#pragma unroll
        for (int o = 16; o > 0; o >>= 1) {
            s1 = add2(s1, __shfl_xor_sync(0xffffffffu, s1, o));
            s2 = add2(s2, __shfl_xor_sync(0xffffffffu, s2, o));
        }
        float m0, m1, q0, q1;
        upk2(s1, m0, m1); upk2(s2, q0, q1);
        const float inv = 1.0f / 128.0f;
        m0 *= inv; m1 *= inv;
        float v0 = q0 * inv - m0 * m0, v1 = q1 * inv - m1 * m1;
        float r0 = rsqrtf(v0 + 1e-5f), r1 = rsqrtf(v1 + 1e-5f);
#pragma unroll
        for (int j = 0; j < 4; j++) {
            float x0, x1; upk2(acc[p][j], x0, x1);
            x0 = (x0 - m0) * r0 * gv[j] + bv[j];
            x1 = (x1 - m1) * r1 * gv[j] + bv[j];
            x0 = x0 * __fdividef(1.0f, 1.0f + __expf(-x0));
            x1 = x1 * __fdividef(1.0f, 1.0f + __expf(-x1));
            acc[p][j] = pk2(x0, x1);
        }
    }
}

__device__ __forceinline__ void store_tile(float* __restrict__ sw, u64 acc[8][4], int l) {
#pragma unroll
    for (int j = 0; j < 4; j++) {
        int c = l + 32 * j;
        u64* d = (u64*)(sw + c * 20);
#pragma unroll
        for (int p = 0; p < 8; p++) d[p] = acc[p][j];
    }
}

// per-warp smem: tile 132 rows x 20 floats = 2640 floats; meta 128 floats
static const int TILE_F  = 2640;
static const int META_F  = 128;
static const int SMEM_B  = (4 * TILE_F + 4 * META_F) * 4;  // 44288 bytes

// ---------------- pre kernel: P1 = h@W1a + b1, P2 = h@W1b ----------------
__global__ __launch_bounds__(128, 3)
void pre_kernel(const float* __restrict__ h, const float* __restrict__ e_b1, int N) {
    extern __shared__ float smem[];
    int w = threadIdx.x >> 5, l = threadIdx.x & 31;
    float* sw = smem + w * TILE_F;
    int base = blockIdx.x * 64 + w * 16;

    // gather h tile once
#pragma unroll 1
    for (int e = 0; e < 16; e++) {
        int n = base + e; int nc = (n < N) ? n : 0;
#pragma unroll
        for (int m = 0; m < 4; m++) {
            int k = l + 32 * m;
            sw[k * 20 + e] = __ldg(h + (size_t)nc * 128 + k);
        }
    }
    __syncwarp();

    u64 acc[8][4];

    // P1 = h @ W1[0:128] + b1
    init_bias(acc, e_b1, l);
    gemm_k<128>(sw, g_Wd + WD_EW1, l, acc);
#pragma unroll
    for (int p = 0; p < 8; p++) {
        int n0 = base + 2 * p, n1 = n0 + 1;
#pragma unroll
        for (int j = 0; j < 4; j++) {
            float x0, x1; upk2(acc[p][j], x0, x1);
            int c = l + 32 * j;
            if (n0 < N) g_P1[(size_t)n0 * 128 + c] = x0;
            if (n1 < N) g_P1[(size_t)n1 * 128 + c] = x1;
        }
    }

    // P2 = h @ W1[128:256]
    init_zero(acc);
    gemm_k<128>(sw, g_Wd + WD_EW1 + 128 * 128, l, acc);
#pragma unroll
    for (int p = 0; p < 8; p++) {
        int n0 = base + 2 * p, n1 = n0 + 1;
#pragma unroll
        for (int j = 0; j < 4; j++) {
            float x0, x1; upk2(acc[p][j], x0, x1);
            int c = l + 32 * j;
            if (n0 < N) g_P2[(size_t)n0 * 128 + c] = x0;
            if (n1 < N) g_P2[(size_t)n1 * 128 + c] = x1;
        }
    }
}

// ---------------- edge kernel: 64 edges / block, 4 warps x 16 edges ----------------
__global__ __launch_bounds__(128, 3)
void edge_kernel(const void* __restrict__ ei,
                 const float* __restrict__ coord, const float* __restrict__ eattr,
                 const float* __restrict__ eW1,
                 const float* __restrict__ e_g1, const float* __restrict__ e_be1,
                 const float* __restrict__ e_b2, const float* __restrict__ e_g2, const float* __restrict__ e_be2,
                 const float* __restrict__ c_b1, const float* __restrict__ c_g1, const float* __restrict__ c_be1,
                 const float* __restrict__ cW2,
                 float* __restrict__ coord_out, int E) {
    extern __shared__ float smem[];
    int w = threadIdx.x >> 5, l = threadIdx.x & 31;
    float* sw   = smem + w * TILE_F;
    float* meta = smem + 4 * TILE_F + w * META_F;
    int*   srow  = (int*)meta;          // gather-safe row
    int*   svrow = (int*)meta + 16;     // -1 if invalid edge
    int*   scol  = (int*)meta + 32;
    float* scd   = meta + 48;           // 48 floats
    float* srad  = meta + 96;           // 16, 8B aligned
    float* sea   = meta + 112;          // 16

    int base = blockIdx.x * 64 + w * 16;

    if (l < 16) {
        int e = base + l;
        bool v = e < E;
        int ec = v ? e : 0;
        int r, c;
        if (g_idx64) {
            const long long* q = (const long long*)ei;
            r = (int)q[ec]; c = (int)q[(size_t)E + ec];
        } else {
            const int* q = (const int*)ei;
            r = q[ec]; c = q[E + ec];
        }
        float dx = coord[r * 3 + 0] - coord[c * 3 + 0];
        float dy = coord[r * 3 + 1] - coord[c * 3 + 1];
        float dz = coord[r * 3 + 2] - coord[c * 3 + 2];
        float radial = dx * dx + dy * dy + dz * dz;
        float invn = 1.0f / (sqrtf(radial + 1e-8f) + 1.0f);
        srow[l]  = r;
        svrow[l] = v ? r : -1;
        scol[l]  = c;
        scd[l * 3 + 0] = dx * invn;
        scd[l * 3 + 1] = dy * invn;
        scd[l * 3 + 2] = dz * invn;
        srad[l] = radial;
        sea[l]  = eattr[ec];
    }
    __syncwarp();

    u64 acc[8][4];

    // ---- layer 1 DIRECT: P1[row] + P2[col] + radial*W[256] + ea*W[257] ----
    {
        float w6[4], w7[4];
#pragma unroll
        for (int j = 0; j < 4; j++) {
            w6[j] = __ldg(eW1 + 256 * 128 + l + 32 * j);
            w7[j] = __ldg(eW1 + 257 * 128 + l + 32 * j);
        }
#pragma unroll
        for (int p = 0; p < 8; p++) {
            int r0 = srow[2 * p],     r1 = srow[2 * p + 1];
            int c0 = scol[2 * p],     c1 = scol[2 * p + 1];
            const float* p1a = g_P1 + (size_t)r0 * 128 + l;
            const float* p1b = g_P1 + (size_t)r1 * 128 + l;
            const float* p2a = g_P2 + (size_t)c0 * 128 + l;
            const float* p2b = g_P2 + (size_t)c1 * 128 + l;
            u64 rad2 = *(const u64*)(srad + 2 * p);
            u64 ea2  = *(const u64*)(sea  + 2 * p);
#pragma unroll
            for (int j = 0; j < 4; j++) {
                float a0 = __ldg(p1a + 32 * j) + __ldg(p2a + 32 * j);
                float a1 = __ldg(p1b + 32 * j) + __ldg(p2b + 32 * j);
                u64 v = pk2(a0, a1);
                v = fma2(rad2, pk2(w6[j], w6[j]), v);
                v = fma2(ea2,  pk2(w7[j], w7[j]), v);
                acc[p][j] = v;
            }
        }
    }
    ln_silu(acc, e_g1, e_be1, l);
    store_tile(sw, acc, l);
    __syncwarp();

    // ---- layer 2 -> edge_feat ----
    init_bias(acc, e_b2, l);
    gemm_k<128>(sw, g_Wd + WD_EW2, l, acc);
    ln_silu(acc, e_g2, e_be2, l);

    // scatter edge_feat into agg (coalesced channels per j)
#pragma unroll
    for (int p = 0; p < 8; p++) {
        int r0 = svrow[2 * p], r1 = svrow[2 * p + 1];
#pragma unroll
        for (int j = 0; j < 4; j++) {
            float x0, x1; upk2(acc[p][j], x0, x1);
            int c = l + 32 * j;
            if (r0 >= 0) atomicAdd(&g_agg[(size_t)r0 * 128 + c], x0);
            if (r1 >= 0) atomicAdd(&g_agg[(size_t)r1 * 128 + c], x1);
        }
    }
    __syncwarp();
    store_tile(sw, acc, l);
    __syncwarp();

    // ---- coord MLP ----
    init_bias(acc, c_b1, l);
    gemm_k<128>(sw, g_Wd + WD_CW1, l, acc);
    ln_silu(acc, c_g1, c_be1, l);

    float wv[4];
#pragma unroll
    for (int j = 0; j < 4; j++) wv[j] = __ldg(cW2 + l + 32 * j);
    u64 cms[8];
#pragma unroll
    for (int p = 0; p < 8; p++) {
        u64 s = 0ull;
#pragma unroll
        for (int j = 0; j < 4; j++) s = fma2(acc[p][j], pk2(wv[j], wv[j]), s);
#pragma unroll
        for (int o = 16; o > 0; o >>= 1)
            s = add2(s, __shfl_xor_sync(0xffffffffu, s, o));
        cms[p] = s;
    }
    if (l < 16) {
        float c0, c1; upk2(cms[l >> 1], c0, c1);
        float cmv = (l & 1) ? c1 : c0;
        int r = svrow[l];
        if (r >= 0) {
            atomicAdd(&coord_out[(size_t)r * 3 + 0], scd[l * 3 + 0] * cmv);
            atomicAdd(&coord_out[(size_t)r * 3 + 1], scd[l * 3 + 1] * cmv);
            atomicAdd(&coord_out[(size_t)r * 3 + 2], scd[l * 3 + 2] * cmv);
        }
    }
}

// ---------------- node kernel: 64 nodes / block ----------------
__global__ __launch_bounds__(128, 3)
void node_kernel(const float* __restrict__ h,
                 const float* __restrict__ n_b1, const float* __restrict__ n_g1,
                 const float* __restrict__ n_be1, const float* __restrict__ n_b2,
                 float* __restrict__ out, int N) {
    extern __shared__ float smem[];
    int w = threadIdx.x >> 5, l = threadIdx.x & 31;
    float* sw = smem + w * TILE_F;
    int base = blockIdx.x * 64 + w * 16;

    u64 acc[8][4];
    init_bias(acc, n_b1, l);

    // pass A: h (W rows 0..127)
#pragma unroll 1
    for (int e = 0; e < 16; e++) {
        int n = base + e; int nc = (n < N) ? n : 0;
#pragma unroll
        for (int m = 0; m < 4; m++) {
            int k = l + 32 * m;
            sw[k * 20 + e] = __ldg(h + (size_t)nc * 128 + k);
        }
    }
    __syncwarp();
    gemm_k<128>(sw, g_Wd + WD_NW1, l, acc);
    __syncwarp();

    // pass B: agg (W rows 128..255)
#pragma unroll 1
    for (int e = 0; e < 16; e++) {
        int n = base + e; int nc = (n < N) ? n : 0;
#pragma unroll
        for (int m = 0; m < 4; m++) {
            int k = l + 32 * m;
            sw[k * 20 + e] = g_agg[(size_t)nc * 128 + k];
        }
    }
    __syncwarp();
    gemm_k<128>(sw, g_Wd + WD_NW1 + 128 * 128, l, acc);
    ln_silu(acc, n_g1, n_be1, l);
    __syncwarp();
    store_tile(sw, acc, l);
    __syncwarp();

    init_bias(acc, n_b2, l);
    gemm_k<128>(sw, g_Wd + WD_NW2, l, acc);

#pragma unroll
    for (int p = 0; p < 8; p++) {
        int n0 = base + 2 * p, n1 = n0 + 1;
#pragma unroll
        for (int j = 0; j < 4; j++) {
            float x0, x1; upk2(acc[p][j], x0, x1);
            int c = l + 32 * j;
            if (n0 < N) out[(size_t)n0 * 128 + c] = x0 + __ldg(h + (size_t)n0 * 128 + c);
            if (n1 < N) out[(size_t)n1 * 128 + c] = x1 + __ldg(h + (size_t)n1 * 128 + c);
        }
    }
}

// ---------------- launch ----------------
extern "C" void kernel_launch(void* const* d_in, const int* in_sizes, int n_in,
                              void* d_out, int out_size) {
    const float* h     = (const float*)d_in[0];
    const void*  ei    = d_in[1];
    const float* coord = (const float*)d_in[2];
    const float* eattr = (const float*)d_in[3];
    const float* eW1  = (const float*)d_in[4];
    const float* eb1  = (const float*)d_in[5];
    const float* eg1  = (const float*)d_in[6];
    const float* ebe1 = (const float*)d_in[7];
    const float* eW2  = (const float*)d_in[8];
    const float* eb2  = (const float*)d_in[9];
    const float* eg2  = (const float*)d_in[10];
    const float* ebe2 = (const float*)d_in[11];
    const float* nW1  = (const float*)d_in[12];
    const float* nb1  = (const float*)d_in[13];
    const float* ng1  = (const float*)d_in[14];
    const float* nbe1 = (const float*)d_in[15];
    const float* nW2  = (const float*)d_in[16];
    const float* nb2  = (const float*)d_in[17];
    const float* cW1  = (const float*)d_in[18];
    const float* cb1  = (const float*)d_in[19];
    const float* cg1  = (const float*)d_in[20];
    const float* cbe1 = (const float*)d_in[21];
    const float* cW2  = (const float*)d_in[22];

    int N = in_sizes[0] / 128;
    int E = in_sizes[1] / 2;

    float* out       = (float*)d_out;
    float* coord_out = out + (size_t)N * 128;

    cudaFuncSetAttribute(pre_kernel,  cudaFuncAttributeMaxDynamicSharedMemorySize, SMEM_B);
    cudaFuncSetAttribute(edge_kernel, cudaFuncAttributeMaxDynamicSharedMemorySize, SMEM_B);
    cudaFuncSetAttribute(node_kernel, cudaFuncAttributeMaxDynamicSharedMemorySize, SMEM_B);

    init_kernel<<<(N * 128 + 255) / 256, 256>>>(coord, coord_out, (const unsigned*)ei, N);
    prep_kernel<<<131072 / 256, 256>>>(eW1, eW2, cW1, nW1, nW2);
    pre_kernel<<<(N + 63) / 64, 128, SMEM_B>>>(h, eb1, N);
    edge_kernel<<<(E + 63) / 64, 128, SMEM_B>>>(ei, coord, eattr,
                                                eW1, eg1, ebe1,
                                                eb2, eg2, ebe2,
                                                cb1, cg1, cbe1, cW2,
                                                coord_out, E);
    node_kernel<<<(N + 63) / 64, 128, SMEM_B>>>(h, nb1, ng1, nbe1, nb2, out, N);
}

// round 15
// speedup vs baseline: 2.9057x; 1.7143x over previous
#include <cuda_runtime.h>
#include <math.h>

typedef unsigned long long u64;
typedef unsigned int u32;

// ---------------- device scratch (no allocations allowed) ----------------
__device__ float g_agg[25000 * 128]; // segment-sum of edge_feat
__device__ float g_P1 [25000 * 128]; // h @ e_W1[0:128] + e_b1
__device__ float g_P2 [25000 * 128]; // h @ e_W1[128:256]
__device__ u64   g_Bh [8192];        // bf16-hi B fragments: [mat][ch][nt][lane], mat0=eW2, mat1=cW1
__device__ u64   g_Bl [8192];        // bf16-lo B fragments
__device__ int   g_idx64;            // 1 if edge_index is int64

// ---------------- packed f32x2 helpers ----------------
__device__ __forceinline__ u64 pk2(float lo, float hi) {
    u64 r; asm("mov.b64 %0,{%1,%2};" : "=l"(r) : "f"(lo), "f"(hi)); return r;
}
__device__ __forceinline__ void upk2(u64 v, float& lo, float& hi) {
    asm("mov.b64 {%0,%1},%2;" : "=f"(lo), "=f"(hi) : "l"(v));
}
__device__ __forceinline__ u64 fma2(u64 a, u64 b, u64 c) {
    u64 d; asm("fma.rn.f32x2 %0,%1,%2,%3;" : "=l"(d) : "l"(a), "l"(b), "l"(c)); return d;
}
__device__ __forceinline__ u64 add2(u64 a, u64 b) {
    u64 d; asm("add.rn.f32x2 %0,%1,%2;" : "=l"(d) : "l"(a), "l"(b)); return d;
}
__device__ __forceinline__ u64 mul2(u64 a, u64 b) {
    u64 d; asm("mul.rn.f32x2 %0,%1,%2;" : "=l"(d) : "l"(a), "l"(b)); return d;
}

// ---------------- bf16 mma helpers ----------------
// pack (e0, e1) as bf16x2 with e0 in low 16 bits (k-even first)
__device__ __forceinline__ u32 bfpack(float e0, float e1) {
    u32 r; asm("cvt.rn.bf16x2.f32 %0, %1, %2;" : "=r"(r) : "f"(e1), "f"(e0)); return r;
}
// packed lo remainder: v - f32(bf16_hi)
__device__ __forceinline__ u32 bflo2(u32 h, float v0, float v1) {
    float l0 = v0 - __uint_as_float(h << 16);
    float l1 = v1 - __uint_as_float(h & 0xFFFF0000u);
    return bfpack(l0, l1);
}
__device__ __forceinline__ void mma16816(float c[4], u32 a0, u32 a1, u32 a2, u32 a3,
                                         u32 b0, u32 b1) {
    asm volatile(
        "mma.sync.aligned.m16n8k16.row.col.f32.bf16.bf16.f32 "
        "{%0,%1,%2,%3},{%4,%5,%6,%7},{%8,%9},{%0,%1,%2,%3};"
        : "+f"(c[0]), "+f"(c[1]), "+f"(c[2]), "+f"(c[3])
        : "r"(a0), "r"(a1), "r"(a2), "r"(a3), "r"(b0), "r"(b1));
}
__device__ __forceinline__ float silu(float y) {
    return y * __fdividef(1.0f, 1.0f + __expf(-y));
}

// ---------------- init: idx detect, zero agg, seed coord_out ----------------
__global__ void init_kernel(const float* __restrict__ coord, float* __restrict__ coord_out,
                            const unsigned* __restrict__ ei, int N) {
    int i = blockIdx.x * blockDim.x + threadIdx.x;
    if (i == 0) {
        int f = 1;
        for (int t = 0; t < 64; t++) if (ei[2 * t + 1] != 0u) { f = 0; break; }
        g_idx64 = f;
    }
    if (i < N * 128) g_agg[i] = 0.0f;
    if (i < N * 3)   coord_out[i] = coord[i];
}

// ---------------- prep: bf16 hi/lo B fragments for eW2, cW1 ----------------
__global__ void prep_kernel(const float* __restrict__ eW2, const float* __restrict__ cW1) {
    int t = blockIdx.x * blockDim.x + threadIdx.x;
    if (t >= 8192) return;
    int mat = t >> 12, r = t & 4095;
    int ch = r >> 9, nt = (r >> 5) & 15, lane = r & 31;
    int qd = lane & 3, rw = lane >> 2;
    int k0 = ch * 16 + 2 * qd, n = nt * 8 + rw;
    const float* W = mat ? cW1 : eW2;
    float v00 = W[k0 * 128 + n],       v01 = W[(k0 + 1) * 128 + n];
    float v10 = W[(k0 + 8) * 128 + n], v11 = W[(k0 + 9) * 128 + n];
    u32 b0h = bfpack(v00, v01), b1h = bfpack(v10, v11);
    u32 b0l = bflo2(b0h, v00, v01), b1l = bflo2(b1h, v10, v11);
    int idx = mat * 4096 + (ch * 16 + nt) * 32 + lane;
    g_Bh[idx] = ((u64)b1h << 32) | b0h;
    g_Bl[idx] = ((u64)b1l << 32) | b0l;
}

// ============ full-width warp GEMM (pre/node kernels, R12-proven) ============
template <int K>
__device__ __forceinline__ void gemm_k(const float* __restrict__ sw,
                                       const float* __restrict__ W,
                                       int l, u64 acc[8][4]) {
    const float* wb = W + l;
#pragma unroll 4
    for (int k = 0; k < K; k++) {
        const float* wr = wb + k * 128;
        float f0 = __ldg(wr);
        float f1 = __ldg(wr + 32);
        float f2 = __ldg(wr + 64);
        float f3 = __ldg(wr + 96);
        const float4* a = (const float4*)(sw + k * 20);
        float4 A0 = a[0], A1 = a[1], A2 = a[2], A3 = a[3];
        u64 x[8];
        x[0] = ((const u64*)&A0)[0]; x[1] = ((const u64*)&A0)[1];
        x[2] = ((const u64*)&A1)[0]; x[3] = ((const u64*)&A1)[1];
        x[4] = ((const u64*)&A2)[0]; x[5] = ((const u64*)&A2)[1];
        x[6] = ((const u64*)&A3)[0]; x[7] = ((const u64*)&A3)[1];
        u64 w0 = pk2(f0, f0), w1 = pk2(f1, f1), w2 = pk2(f2, f2), w3 = pk2(f3, f3);
#pragma unroll
        for (int p = 0; p < 8; p++) {
            acc[p][0] = fma2(x[p], w0, acc[p][0]);
            acc[p][1] = fma2(x[p], w1, acc[p][1]);
            acc[p][2] = fma2(x[p], w2, acc[p][2]);
            acc[p][3] = fma2(x[p], w3, acc[p][3]);
        }
    }
}

__device__ __forceinline__ void init_bias(u64 acc[8][4], const float* __restrict__ b, int l) {
#pragma unroll
    for (int j = 0; j < 4; j++) {
        float bb = __ldg(b + l + 32 * j);
        u64 v = pk2(bb, bb);
#pragma unroll
        for (int p = 0; p < 8; p++) acc[p][j] = v;
    }
}

__device__ __forceinline__ void init_zero(u64 acc[8][4]) {
#pragma unroll
    for (int j = 0; j < 4; j++)
#pragma unroll
        for (int p = 0; p < 8; p++) acc[p][j] = 0ull;
}

__device__ __forceinline__ void ln_silu(u64 acc[8][4],
                                        const float* __restrict__ g,
                                        const float* __restrict__ be, int l) {
    float gv[4], bv[4];
#pragma unroll
    for (int j = 0; j < 4; j++) { gv[j] = __ldg(g + l + 32 * j); bv[j] = __ldg(be + l + 32 * j); }
#pragma unroll
    for (int p = 0; p < 8; p++) {
        u64 s1 = add2(add2(acc[p][0], acc[p][1]), add2(acc[p][2], acc[p][3]));
        u64 s2 = mul2(acc[p][0], acc[p][0]);
        s2 = fma2(acc[p][1], acc[p][1], s2);
        s2 = fma2(acc[p][2], acc[p][2], s2);
        s2 = fma2(acc[p][3], acc[p][3], s2);
#pragma unroll
        for (int o = 16; o > 0; o >>= 1) {
            s1 = add2(s1, __shfl_xor_sync(0xffffffffu, s1, o));
            s2 = add2(s2, __shfl_xor_sync(0xffffffffu, s2, o));
        }
        float m0, m1, q0, q1;
        upk2(s1, m0, m1); upk2(s2, q0, q1);
        const float inv = 1.0f / 128.0f;
        m0 *= inv; m1 *= inv;
        float v0 = q0 * inv - m0 * m0, v1 = q1 * inv - m1 * m1;
        float r0 = rsqrtf(v0 + 1e-5f), r1 = rsqrtf(v1 + 1e-5f);
#pragma unroll
        for (int j = 0; j < 4; j++) {
            float x0, x1; upk2(acc[p][j], x0, x1);
            x0 = silu((x0 - m0) * r0 * gv[j] + bv[j]);
            x1 = silu((x1 - m1) * r1 * gv[j] + bv[j]);
            acc[p][j] = pk2(x0, x1);
        }
    }
}

__device__ __forceinline__ void store_tile(float* __restrict__ sw, u64 acc[8][4], int l) {
#pragma unroll
    for (int j = 0; j < 4; j++) {
        int c = l + 32 * j;
        u64* d = (u64*)(sw + c * 20);
#pragma unroll
        for (int p = 0; p < 8; p++) d[p] = acc[p][j];
    }
}

// LN+silu on mma D fragments: c[16][4], rows rw (c0,c1) and rw+8 (c2,c3)
__device__ __forceinline__ void ln_silu_frag(float c[16][4],
                                             const float* __restrict__ g,
                                             const float* __restrict__ be, int qd) {
    float s1l = 0.f, s2l = 0.f, s1h = 0.f, s2h = 0.f;
#pragma unroll
    for (int nt = 0; nt < 16; nt++) {
        s1l += c[nt][0] + c[nt][1];
        s2l = fmaf(c[nt][0], c[nt][0], fmaf(c[nt][1], c[nt][1], s2l));
        s1h += c[nt][2] + c[nt][3];
        s2h = fmaf(c[nt][2], c[nt][2], fmaf(c[nt][3], c[nt][3], s2h));
    }
    s1l += __shfl_xor_sync(0xffffffffu, s1l, 1); s1l += __shfl_xor_sync(0xffffffffu, s1l, 2);
    s2l += __shfl_xor_sync(0xffffffffu, s2l, 1); s2l += __shfl_xor_sync(0xffffffffu, s2l, 2);
    s1h += __shfl_xor_sync(0xffffffffu, s1h, 1); s1h += __shfl_xor_sync(0xffffffffu, s1h, 2);
    s2h += __shfl_xor_sync(0xffffffffu, s2h, 1); s2h += __shfl_xor_sync(0xffffffffu, s2h, 2);
    const float inv = 1.0f / 128.0f;
    float ml = s1l * inv, mh = s1h * inv;
    float rl = rsqrtf(s2l * inv - ml * ml + 1e-5f);
    float rh = rsqrtf(s2h * inv - mh * mh + 1e-5f);
#pragma unroll
    for (int nt = 0; nt < 16; nt++) {
        float2 gg = *(const float2*)(g  + 8 * nt + 2 * qd);
        float2 bb = *(const float2*)(be + 8 * nt + 2 * qd);
        c[nt][0] = silu((c[nt][0] - ml) * rl * gg.x + bb.x);
        c[nt][1] = silu((c[nt][1] - ml) * rl * gg.y + bb.y);
        c[nt][2] = silu((c[nt][2] - mh) * rh * gg.x + bb.x);
        c[nt][3] = silu((c[nt][3] - mh) * rh * gg.y + bb.y);
    }
}

// per-warp smem: tile 132 rows x 20 floats = 2640 floats; meta 128 floats
static const int TILE_F  = 2640;
static const int META_F  = 128;
static const int SMEM_B  = (4 * TILE_F + 4 * META_F) * 4;  // 44288 bytes

// ---------------- pre kernel: P1 = h@W1a + b1, P2 = h@W1b ----------------
__global__ __launch_bounds__(128, 3)
void pre_kernel(const float* __restrict__ h, const float* __restrict__ eW1,
                const float* __restrict__ e_b1, int N) {
    extern __shared__ float smem[];
    int w = threadIdx.x >> 5, l = threadIdx.x & 31;
    float* sw = smem + w * TILE_F;
    int base = blockIdx.x * 64 + w * 16;

#pragma unroll 1
    for (int e = 0; e < 16; e++) {
        int n = base + e; int nc = (n < N) ? n : 0;
#pragma unroll
        for (int m = 0; m < 4; m++) {
            int k = l + 32 * m;
            sw[k * 20 + e] = __ldg(h + (size_t)nc * 128 + k);
        }
    }
    __syncwarp();

    u64 acc[8][4];
    init_bias(acc, e_b1, l);
    gemm_k<128>(sw, eW1, l, acc);
#pragma unroll
    for (int p = 0; p < 8; p++) {
        int n0 = base + 2 * p, n1 = n0 + 1;
#pragma unroll
        for (int j = 0; j < 4; j++) {
            float x0, x1; upk2(acc[p][j], x0, x1);
            int c = l + 32 * j;
            if (n0 < N) g_P1[(size_t)n0 * 128 + c] = x0;
            if (n1 < N) g_P1[(size_t)n1 * 128 + c] = x1;
        }
    }

    init_zero(acc);
    gemm_k<128>(sw, eW1 + 128 * 128, l, acc);
#pragma unroll
    for (int p = 0; p < 8; p++) {
        int n0 = base + 2 * p, n1 = n0 + 1;
#pragma unroll
        for (int j = 0; j < 4; j++) {
            float x0, x1; upk2(acc[p][j], x0, x1);
            int c = l + 32 * j;
            if (n0 < N) g_P2[(size_t)n0 * 128 + c] = x0;
            if (n1 < N) g_P2[(size_t)n1 * 128 + c] = x1;
        }
    }
}

// ---------------- edge kernel: 64 edges / block, 4 warps x 16 edges ----------------
__global__ __launch_bounds__(128, 3)
void edge_kernel(const void* __restrict__ ei,
                 const float* __restrict__ coord, const float* __restrict__ eattr,
                 const float* __restrict__ eW1,
                 const float* __restrict__ e_g1, const float* __restrict__ e_be1,
                 const float* __restrict__ e_b2, const float* __restrict__ e_g2, const float* __restrict__ e_be2,
                 const float* __restrict__ c_b1, const float* __restrict__ c_g1, const float* __restrict__ c_be1,
                 const float* __restrict__ cW2,
                 float* __restrict__ coord_out, int E) {
    extern __shared__ float smem[];
    int w = threadIdx.x >> 5, l = threadIdx.x & 31;
    float* sw   = smem + w * TILE_F;
    float* meta = smem + 4 * TILE_F + w * META_F;
    int*   srow  = (int*)meta;
    int*   svrow = (int*)meta + 16;
    int*   scol  = (int*)meta + 32;
    float* scd   = meta + 48;
    float* srad  = meta + 96;
    float* sea   = meta + 112;

    int base = blockIdx.x * 64 + w * 16;

    if (l < 16) {
        int e = base + l;
        bool v = e < E;
        int ec = v ? e : 0;
        int r, c;
        if (g_idx64) {
            const long long* q = (const long long*)ei;
            r = (int)q[ec]; c = (int)q[(size_t)E + ec];
        } else {
            const int* q = (const int*)ei;
            r = q[ec]; c = q[E + ec];
        }
        float dx = coord[r * 3 + 0] - coord[c * 3 + 0];
        float dy = coord[r * 3 + 1] - coord[c * 3 + 1];
        float dz = coord[r * 3 + 2] - coord[c * 3 + 2];
        float radial = dx * dx + dy * dy + dz * dz;
        float invn = 1.0f / (sqrtf(radial + 1e-8f) + 1.0f);
        srow[l]  = r;
        svrow[l] = v ? r : -1;
        scol[l]  = c;
        scd[l * 3 + 0] = dx * invn;
        scd[l * 3 + 1] = dy * invn;
        scd[l * 3 + 2] = dz * invn;
        srad[l] = radial;
        sea[l]  = eattr[ec];
    }
    __syncwarp();

    // ---- layer 1 DIRECT: P1[row] + P2[col] + radial*W[256] + ea*W[257] ----
    {
        u64 acc[8][4];
        float w6[4], w7[4];
#pragma unroll
        for (int j = 0; j < 4; j++) {
            w6[j] = __ldg(eW1 + 256 * 128 + l + 32 * j);
            w7[j] = __ldg(eW1 + 257 * 128 + l + 32 * j);
        }
#pragma unroll
        for (int p = 0; p < 8; p++) {
            int r0 = srow[2 * p],     r1 = srow[2 * p + 1];
            int c0 = scol[2 * p],     c1 = scol[2 * p + 1];
            const float* p1a = g_P1 + (size_t)r0 * 128 + l;
            const float* p1b = g_P1 + (size_t)r1 * 128 + l;
            const float* p2a = g_P2 + (size_t)c0 * 128 + l;
            const float* p2b = g_P2 + (size_t)c1 * 128 + l;
            u64 rad2 = *(const u64*)(srad + 2 * p);
            u64 ea2  = *(const u64*)(sea  + 2 * p);
#pragma unroll
            for (int j = 0; j < 4; j++) {
                float a0 = __ldg(p1a + 32 * j) + __ldg(p2a + 32 * j);
                float a1 = __ldg(p1b + 32 * j) + __ldg(p2b + 32 * j);
                u64 v = pk2(a0, a1);
                v = fma2(rad2, pk2(w6[j], w6[j]), v);
                v = fma2(ea2,  pk2(w7[j], w7[j]), v);
                acc[p][j] = v;
            }
        }
        ln_silu(acc, e_g1, e_be1, l);
        store_tile(sw, acc, l);   // tile[channel*20 + edge]
    }
    __syncwarp();

    // ======== layers 2 & 3 via bf16 mma.sync (3-pass hi/lo) ========
    int qd = l & 3, rw = l >> 2;
    int k2 = 2 * qd;

    float c2r[16][4];
#pragma unroll
    for (int nt = 0; nt < 16; nt++) {
        float2 b = *(const float2*)(e_b2 + 8 * nt + k2);
        c2r[nt][0] = b.x; c2r[nt][1] = b.y; c2r[nt][2] = b.x; c2r[nt][3] = b.y;
    }
#pragma unroll 1
    for (int ch = 0; ch < 8; ch++) {
        int k0 = ch * 16 + k2;
        float a00 = sw[k0 * 20 + rw],           a01 = sw[(k0 + 1) * 20 + rw];
        float a10 = sw[k0 * 20 + rw + 8],       a11 = sw[(k0 + 1) * 20 + rw + 8];
        float a20 = sw[(k0 + 8) * 20 + rw],     a21 = sw[(k0 + 9) * 20 + rw];
        float a30 = sw[(k0 + 8) * 20 + rw + 8], a31 = sw[(k0 + 9) * 20 + rw + 8];
        u32 ah0 = bfpack(a00, a01), ah1 = bfpack(a10, a11);
        u32 ah2 = bfpack(a20, a21), ah3 = bfpack(a30, a31);
        u32 al0 = bflo2(ah0, a00, a01), al1 = bflo2(ah1, a10, a11);
        u32 al2 = bflo2(ah2, a20, a21), al3 = bflo2(ah3, a30, a31);
        const u64* bph = g_Bh + ch * 512 + l;
        const u64* bpl = g_Bl + ch * 512 + l;
#pragma unroll
        for (int nt = 0; nt < 16; nt++) {
            u64 wh = __ldg(bph + nt * 32);
            u64 wl = __ldg(bpl + nt * 32);
            u32 wh0 = (u32)wh, wh1 = (u32)(wh >> 32);
            u32 wl0 = (u32)wl, wl1 = (u32)(wl >> 32);
            mma16816(c2r[nt], ah0, ah1, ah2, ah3, wh0, wh1);
            mma16816(c2r[nt], ah0, ah1, ah2, ah3, wl0, wl1);
            mma16816(c2r[nt], al0, al1, al2, al3, wh0, wh1);
        }
    }
    ln_silu_frag(c2r, e_g2, e_be2, qd);

    // agg scatter from fragments (edge rows rw, rw+8)
    {
        int r0 = svrow[rw], r1 = svrow[rw + 8];
#pragma unroll
        for (int nt = 0; nt < 16; nt++) {
            int cch = 8 * nt + k2;
            if (r0 >= 0) {
                atomicAdd(&g_agg[(size_t)r0 * 128 + cch],     c2r[nt][0]);
                atomicAdd(&g_agg[(size_t)r0 * 128 + cch + 1], c2r[nt][1]);
            }
            if (r1 >= 0) {
                atomicAdd(&g_agg[(size_t)r1 * 128 + cch],     c2r[nt][2]);
                atomicAdd(&g_agg[(size_t)r1 * 128 + cch + 1], c2r[nt][3]);
            }
        }
    }

    // convert layer2 output to layer3 A fragments (register chain, no smem)
    u32 a3h[8][4], a3l[8][4];
#pragma unroll
    for (int cc = 0; cc < 8; cc++) {
        float v00 = c2r[2 * cc][0],     v01 = c2r[2 * cc][1];
        float v02 = c2r[2 * cc][2],     v03 = c2r[2 * cc][3];
        float v10 = c2r[2 * cc + 1][0], v11 = c2r[2 * cc + 1][1];
        float v12 = c2r[2 * cc + 1][2], v13 = c2r[2 * cc + 1][3];
        a3h[cc][0] = bfpack(v00, v01);  a3h[cc][1] = bfpack(v02, v03);
        a3h[cc][2] = bfpack(v10, v11);  a3h[cc][3] = bfpack(v12, v13);
        a3l[cc][0] = bflo2(a3h[cc][0], v00, v01);
        a3l[cc][1] = bflo2(a3h[cc][1], v02, v03);
        a3l[cc][2] = bflo2(a3h[cc][2], v10, v11);
        a3l[cc][3] = bflo2(a3h[cc][3], v12, v13);
    }

    // ---- layer 3 (coord MLP) ----
    float c3r[16][4];
#pragma unroll
    for (int nt = 0; nt < 16; nt++) {
        float2 b = *(const float2*)(c_b1 + 8 * nt + k2);
        c3r[nt][0] = b.x; c3r[nt][1] = b.y; c3r[nt][2] = b.x; c3r[nt][3] = b.y;
    }
#pragma unroll 1
    for (int ch = 0; ch < 8; ch++) {
        const u64* bph = g_Bh + 4096 + ch * 512 + l;
        const u64* bpl = g_Bl + 4096 + ch * 512 + l;
        u32 ah0 = a3h[ch][0], ah1 = a3h[ch][1], ah2 = a3h[ch][2], ah3 = a3h[ch][3];
        u32 al0 = a3l[ch][0], al1 = a3l[ch][1], al2 = a3l[ch][2], al3 = a3l[ch][3];
#pragma unroll
        for (int nt = 0; nt < 16; nt++) {
            u64 wh = __ldg(bph + nt * 32);
            u64 wl = __ldg(bpl + nt * 32);
            u32 wh0 = (u32)wh, wh1 = (u32)(wh >> 32);
            u32 wl0 = (u32)wl, wl1 = (u32)(wl >> 32);
            mma16816(c3r[nt], ah0, ah1, ah2, ah3, wh0, wh1);
            mma16816(c3r[nt], ah0, ah1, ah2, ah3, wl0, wl1);
            mma16816(c3r[nt], al0, al1, al2, al3, wh0, wh1);
        }
    }
    ln_silu_frag(c3r, c_g1, c_be1, qd);

    // coord dot + scatter
    {
        float dl = 0.f, dh = 0.f;
#pragma unroll
        for (int nt = 0; nt < 16; nt++) {
            float2 wv = *(const float2*)(cW2 + 8 * nt + k2);
            dl = fmaf(c3r[nt][0], wv.x, fmaf(c3r[nt][1], wv.y, dl));
            dh = fmaf(c3r[nt][2], wv.x, fmaf(c3r[nt][3], wv.y, dh));
        }
        dl += __shfl_xor_sync(0xffffffffu, dl, 1); dl += __shfl_xor_sync(0xffffffffu, dl, 2);
        dh += __shfl_xor_sync(0xffffffffu, dh, 1); dh += __shfl_xor_sync(0xffffffffu, dh, 2);
        if (qd == 0) {
            int r0 = svrow[rw];
            if (r0 >= 0) {
                atomicAdd(&coord_out[(size_t)r0 * 3 + 0], scd[rw * 3 + 0] * dl);
                atomicAdd(&coord_out[(size_t)r0 * 3 + 1], scd[rw * 3 + 1] * dl);
                atomicAdd(&coord_out[(size_t)r0 * 3 + 2], scd[rw * 3 + 2] * dl);
            }
            int r1 = svrow[rw + 8];
            if (r1 >= 0) {
                atomicAdd(&coord_out[(size_t)r1 * 3 + 0], scd[(rw + 8) * 3 + 0] * dh);
                atomicAdd(&coord_out[(size_t)r1 * 3 + 1], scd[(rw + 8) * 3 + 1] * dh);
                atomicAdd(&coord_out[(size_t)r1 * 3 + 2], scd[(rw + 8) * 3 + 2] * dh);
            }
        }
    }
}

// ---------------- node kernel: 64 nodes / block (R12-proven) ----------------
__global__ __launch_bounds__(128, 3)
void node_kernel(const float* __restrict__ h,
                 const float* __restrict__ nW1,
                 const float* __restrict__ n_b1, const float* __restrict__ n_g1,
                 const float* __restrict__ n_be1,
                 const float* __restrict__ nW2, const float* __restrict__ n_b2,
                 float* __restrict__ out, int N) {
    extern __shared__ float smem[];
    int w = threadIdx.x >> 5, l = threadIdx.x & 31;
    float* sw = smem + w * TILE_F;
    int base = blockIdx.x * 64 + w * 16;

    u64 acc[8][4];
    init_bias(acc, n_b1, l);

#pragma unroll 1
    for (int e = 0; e < 16; e++) {
        int n = base + e; int nc = (n < N) ? n : 0;
#pragma unroll
        for (int m = 0; m < 4; m++) {
            int k = l + 32 * m;
            sw[k * 20 + e] = __ldg(h + (size_t)nc * 128 + k);
        }
    }
    __syncwarp();
    gemm_k<128>(sw, nW1, l, acc);
    __syncwarp();

#pragma unroll 1
    for (int e = 0; e < 16; e++) {
        int n = base + e; int nc = (n < N) ? n : 0;
#pragma unroll
        for (int m = 0; m < 4; m++) {
            int k = l + 32 * m;
            sw[k * 20 + e] = g_agg[(size_t)nc * 128 + k];
        }
    }
    __syncwarp();
    gemm_k<128>(sw, nW1 + 128 * 128, l, acc);
    ln_silu(acc, n_g1, n_be1, l);
    __syncwarp();
    store_tile(sw, acc, l);
    __syncwarp();

    init_bias(acc, n_b2, l);
    gemm_k<128>(sw, nW2, l, acc);

#pragma unroll
    for (int p = 0; p < 8; p++) {
        int n0 = base + 2 * p, n1 = n0 + 1;
#pragma unroll
        for (int j = 0; j < 4; j++) {
            float x0, x1; upk2(acc[p][j], x0, x1);
            int c = l + 32 * j;
            if (n0 < N) out[(size_t)n0 * 128 + c] = x0 + __ldg(h + (size_t)n0 * 128 + c);
            if (n1 < N) out[(size_t)n1 * 128 + c] = x1 + __ldg(h + (size_t)n1 * 128 + c);
        }
    }
}

// ---------------- launch ----------------
extern "C" void kernel_launch(void* const* d_in, const int* in_sizes, int n_in,
                              void* d_out, int out_size) {
    const float* h     = (const float*)d_in[0];
    const void*  ei    = d_in[1];
    const float* coord = (const float*)d_in[2];
    const float* eattr = (const float*)d_in[3];
    const float* eW1  = (const float*)d_in[4];
    const float* eb1  = (const float*)d_in[5];
    const float* eg1  = (const float*)d_in[6];
    const float* ebe1 = (const float*)d_in[7];
    const float* eW2  = (const float*)d_in[8];
    const float* eb2  = (const float*)d_in[9];
    const float* eg2  = (const float*)d_in[10];
    const float* ebe2 = (const float*)d_in[11];
    const float* nW1  = (const float*)d_in[12];
    const float* nb1  = (const float*)d_in[13];
    const float* ng1  = (const float*)d_in[14];
    const float* nbe1 = (const float*)d_in[15];
    const float* nW2  = (const float*)d_in[16];
    const float* nb2  = (const float*)d_in[17];
    const float* cW1  = (const float*)d_in[18];
    const float* cb1  = (const float*)d_in[19];
    const float* cg1  = (const float*)d_in[20];
    const float* cbe1 = (const float*)d_in[21];
    const float* cW2  = (const float*)d_in[22];

    int N = in_sizes[0] / 128;
    int E = in_sizes[1] / 2;

    float* out       = (float*)d_out;
    float* coord_out = out + (size_t)N * 128;

    cudaFuncSetAttribute(pre_kernel,  cudaFuncAttributeMaxDynamicSharedMemorySize, SMEM_B);
    cudaFuncSetAttribute(edge_kernel, cudaFuncAttributeMaxDynamicSharedMemorySize, SMEM_B);
    cudaFuncSetAttribute(node_kernel, cudaFuncAttributeMaxDynamicSharedMemorySize, SMEM_B);

    init_kernel<<<(N * 128 + 255) / 256, 256>>>(coord, coord_out, (const unsigned*)ei, N);
    prep_kernel<<<8192 / 256, 256>>>(eW2, cW1);
    pre_kernel<<<(N + 63) / 64, 128, SMEM_B>>>(h, eW1, eb1, N);
    edge_kernel<<<(E + 63) / 64, 128, SMEM_B>>>(ei, coord, eattr,
                                                eW1, eg1, ebe1,
                                                eb2, eg2, ebe2,
                                                cb1, cg1, cbe1, cW2,
                                                coord_out, E);
    node_kernel<<<(N + 63) / 64, 128, SMEM_B>>>(h, nW1, nb1, ng1, nbe1, nW2, nb2, out, N);
}